// round 7
// baseline (speedup 1.0000x reference)
#include <cuda_runtime.h>
#include <cuda_bf16.h>
#include <cstdint>

#define B_  32
#define C_  512
#define HW_ 4096
#define N_  80

// Scratch (__device__ globals per allocation rules)
__device__ float         g_logits[(size_t)B_ * N_ * HW_];
__device__ __nv_bfloat16 g_att_hi[(size_t)B_ * N_ * HW_];
__device__ __nv_bfloat16 g_att_lo[(size_t)B_ * N_ * HW_];
__device__ __nv_bfloat16 g_f_hi[(size_t)B_ * C_ * HW_];   // feats split, written by gemm1
__device__ __nv_bfloat16 g_f_lo[(size_t)B_ * C_ * HW_];
__device__ uint32_t      g_w_hi[N_ * C_ / 2];             // W split (packed bf16x2)
__device__ uint32_t      g_w_lo[N_ * C_ / 2];

// ---------------------------------------------------------------------------
// helpers
// ---------------------------------------------------------------------------
__device__ __forceinline__ uint32_t smem_u32(const void* p) {
    uint32_t a;
    asm("{ .reg .u64 t; cvta.to.shared.u64 t, %1; cvt.u32.u64 %0, t; }" : "=r"(a) : "l"(p));
    return a;
}
__device__ __forceinline__ uint32_t swz(uint32_t off) { return off ^ ((off >> 3) & 0x70u); }
__device__ __forceinline__ void sts64(uint32_t addr, uint32_t v0, uint32_t v1) {
    asm volatile("st.shared.v2.b32 [%0], {%1,%2};" :: "r"(addr), "r"(v0), "r"(v1));
}
#define CP_ASYNC16(dst, src) \
    asm volatile("cp.async.cg.shared.global [%0], [%1], 16;" :: "r"(dst), "l"(src))
#define CP_COMMIT() asm volatile("cp.async.commit_group;" ::: "memory")
#define CP_WAIT0()  asm volatile("cp.async.wait_group 0;" ::: "memory")

__device__ __forceinline__ void ldmx4(uint32_t* r, uint32_t addr) {       // non-trans
    asm volatile("ldmatrix.sync.aligned.m8n8.x4.shared.b16 {%0,%1,%2,%3}, [%4];"
                 : "=r"(r[0]), "=r"(r[1]), "=r"(r[2]), "=r"(r[3]) : "r"(addr));
}
__device__ __forceinline__ void ldmx2(uint32_t* r, uint32_t addr) {       // non-trans
    asm volatile("ldmatrix.sync.aligned.m8n8.x2.shared.b16 {%0,%1}, [%2];"
                 : "=r"(r[0]), "=r"(r[1]) : "r"(addr));
}
__device__ __forceinline__ void ldmx4t(uint32_t* r, uint32_t addr) {      // trans
    asm volatile("ldmatrix.sync.aligned.m8n8.x4.trans.shared.b16 {%0,%1,%2,%3}, [%4];"
                 : "=r"(r[0]), "=r"(r[1]), "=r"(r[2]), "=r"(r[3]) : "r"(addr));
}
// D(f32) += A(bf16) * B(bf16), m16n8k16 — NOT volatile: lets ptxas schedule/interleave
__device__ __forceinline__ void mma16816(float* d, const uint32_t* a,
                                         uint32_t b0, uint32_t b1) {
    asm("mma.sync.aligned.m16n8k16.row.col.f32.bf16.bf16.f32 "
        "{%0,%1,%2,%3}, {%4,%5,%6,%7}, {%8,%9}, {%0,%1,%2,%3};"
        : "+f"(d[0]), "+f"(d[1]), "+f"(d[2]), "+f"(d[3])
        : "r"(a[0]), "r"(a[1]), "r"(a[2]), "r"(a[3]), "r"(b0), "r"(b1));
}
// split two f32 -> packed bf16 hi pair / lo (residual) pair; low half = first value
__device__ __forceinline__ void split2(float f0, float f1, uint32_t& hi, uint32_t& lo) {
    asm("cvt.rn.bf16x2.f32 %0, %1, %2;" : "=r"(hi) : "f"(f1), "f"(f0));
    float h0 = __uint_as_float(hi << 16);
    float h1 = __uint_as_float(hi & 0xffff0000u);
    asm("cvt.rn.bf16x2.f32 %0, %1, %2;" : "=r"(lo) : "f"(f1 - h1), "f"(f0 - h0));
}

#define G1_STAGE 53248u
#define G2_STAGE 53248u

// ===========================================================================
// split_w: W f32 [80,512] -> g_w_hi/lo packed bf16x2. grid 80, block 256.
// ===========================================================================
__global__ void split_w(const float* __restrict__ W) {
    int i = blockIdx.x * 256 + threadIdx.x;          // 20480 float2 units
    float2 v = ((const float2*)W)[i];
    uint32_t hi, lo; split2(v.x, v.y, hi, lo);
    g_w_hi[i] = hi; g_w_lo[i] = lo;
}

// ===========================================================================
// GEMM1: logits[b,n,h] = sum_c W[n,c] * feats[b,c,h]; also writes split feats.
//   CTA tile [n=80 x h=128], K-chunk 64. 640 threads = 20 warps (5 m x 4 hq),
//   warp tile m16 x n32. Stage: Wh@0(10240) Wl@10240,
//   Fh@20480 (two 64-h halves, 8192 each), Fl@36864. Stage=53248, x2 buf.
// ===========================================================================
__global__ __launch_bounds__(640, 1) void gemm1_mma(const float* __restrict__ feats) {
    extern __shared__ __align__(1024) char smem[];
    const uint32_t sb = smem_u32(smem);
    const int tid = threadIdx.x, wid = tid >> 5, lane = tid & 31;
    const int g = lane >> 2, t = lane & 3;
    const int mw = wid % 5, hwq = wid / 5;   // m0 = mw*16 (n), h quarter = hwq*32
    const int m0 = mw * 16;
    const int b = blockIdx.y, hC = blockIdx.x * 128;

    const float* Fb = feats + (size_t)b * C_ * HW_;

    float acc[4][4];
#pragma unroll
    for (int i = 0; i < 4; i++)
#pragma unroll
        for (int j = 0; j < 4; j++) acc[i][j] = 0.0f;

    float4 fst[4];

    auto cp_w = [&](uint32_t buf, int kb) {
        const int c0b = kb * 128;                      // byte offset within W row
#pragma unroll
        for (int it = 0; it < 2; it++) {
            int p = tid + it * 640;                    // 1280 = 2 x 640 chunks
            int sel = p >= 640;
            int q = sel ? p - 640 : p;
            int n = q >> 3, cb = (q & 7) * 16;
            const char* src = (sel ? (const char*)g_w_lo : (const char*)g_w_hi) +
                              n * 1024 + c0b + cb;
            CP_ASYNC16(buf + (sel ? 10240u : 0u) + swz((uint32_t)(n * 128 + cb)), src);
        }
    };
    auto ldg_f = [&](int kb) {
        const int c0 = kb * 64;
#pragma unroll
        for (int it = 0; it < 4; it++) {               // 2048 float4
            int p = tid + it * 640;
            if (p < 2048) {
                int c = p >> 5, hf = p & 31;
                fst[it] = *(const float4*)(Fb + (size_t)(c0 + c) * HW_ + hC + hf * 4);
            }
        }
    };
    auto sts_stg_f = [&](uint32_t buf, int kb) {
        const int c0 = kb * 64;
#pragma unroll
        for (int it = 0; it < 4; it++) {
            int p = tid + it * 640;
            if (p < 2048) {
                int c = p >> 5, hf = p & 31;
                uint32_t h0, l0, h1, l1;
                split2(fst[it].x, fst[it].y, h0, l0);
                split2(fst[it].z, fst[it].w, h1, l1);
                uint32_t half = (uint32_t)(hf >> 4) * 8192u;
                uint32_t off = swz((uint32_t)(c * 128 + (hf & 15) * 8));
                sts64(buf + 20480u + half + off, h0, h1);
                sts64(buf + 36864u + half + off, l0, l1);
                size_t gi = ((size_t)(b * C_ + c0 + c) * HW_ + hC + hf * 4);
                *(uint2*)((char*)g_f_hi + gi * 2) = make_uint2(h0, h1);
                *(uint2*)((char*)g_f_lo + gi * 2) = make_uint2(l0, l1);
            }
        }
    };
    auto compute = [&](uint32_t buf) {
        const uint32_t Wh = buf, Wl = buf + 10240u;
        const uint32_t half = (uint32_t)(hwq >> 1) * 8192u;
        const uint32_t Fh = buf + 20480u + half;
        const uint32_t Fl = buf + 36864u + half;
        const uint32_t hsub = (uint32_t)(hwq & 1) * 32u;
        const uint32_t arow = (uint32_t)(m0 + (lane & 15)) * 128;
#pragma unroll
        for (int ks = 0; ks < 4; ks++) {
            uint32_t ah[4], al[4];
            uint32_t aoff = swz(arow + ks * 32 + (lane >> 4) * 16);
            ldmx4(ah, Wh + aoff);
            ldmx4(al, Wl + aoff);
            uint32_t rh[2][4], rl[2][4];
#pragma unroll
            for (int np = 0; np < 2; np++) {
                uint32_t boff = swz((uint32_t)(ks * 16 + (lane & 15)) * 128 +
                                    (hsub + np * 16 + ((lane >> 4) << 3)) * 2);
                ldmx4t(rh[np], Fh + boff);
                ldmx4t(rl[np], Fl + boff);
            }
            // term-grouped issue: chains per accumulator spaced by 4 indep MMAs
            mma16816(acc[0], ah, rh[0][0], rh[0][1]);      // hi*hi
            mma16816(acc[1], ah, rh[0][2], rh[0][3]);
            mma16816(acc[2], ah, rh[1][0], rh[1][1]);
            mma16816(acc[3], ah, rh[1][2], rh[1][3]);
            mma16816(acc[0], ah, rl[0][0], rl[0][1]);      // hi*lo
            mma16816(acc[1], ah, rl[0][2], rl[0][3]);
            mma16816(acc[2], ah, rl[1][0], rl[1][1]);
            mma16816(acc[3], ah, rl[1][2], rl[1][3]);
            mma16816(acc[0], al, rh[0][0], rh[0][1]);      // lo*hi
            mma16816(acc[1], al, rh[0][2], rh[0][3]);
            mma16816(acc[2], al, rh[1][0], rh[1][1]);
            mma16816(acc[3], al, rh[1][2], rh[1][3]);
        }
    };

    // pipeline: one sync per iteration
    cp_w(sb, 0); CP_COMMIT();
    ldg_f(0);
    sts_stg_f(sb, 0);
    CP_WAIT0();
    __syncthreads();
#pragma unroll 1
    for (int kb = 0; kb < 8; kb++) {
        const uint32_t cur = sb + (uint32_t)(kb & 1) * G1_STAGE;
        const uint32_t nxt = sb + (uint32_t)((kb + 1) & 1) * G1_STAGE;
        if (kb + 1 < 8) { cp_w(nxt, kb + 1); CP_COMMIT(); ldg_f(kb + 1); }
        compute(cur);
        if (kb + 1 < 8) {
            sts_stg_f(nxt, kb + 1);
            CP_WAIT0();
            __syncthreads();
        }
    }

    // epilogue: frag f = 2*np + q8 covers h block hwq*32 + np*16 + q8*8
#pragma unroll
    for (int f = 0; f < 4; f++) {
        int np = f >> 1, q8 = f & 1;
        int h = hC + hwq * 32 + np * 16 + q8 * 8 + 2 * t;
        int n = m0 + g;
        *(float2*)(g_logits + (size_t)(b * N_ + n) * HW_ + h) =
            make_float2(acc[f][0], acc[f][1]);
        *(float2*)(g_logits + (size_t)(b * N_ + n + 8) * HW_ + h) =
            make_float2(acc[f][2], acc[f][3]);
    }
}

// ===========================================================================
// Softmax over HW, g_logits -> split bf16 att maps. grid B*N, block 256.
// ===========================================================================
__global__ __launch_bounds__(256) void softmax_split() {
    const size_t row = blockIdx.x;
    const float* rowp = g_logits + row * HW_;
    const int tid = threadIdx.x;
    __shared__ float sm[8];

    float4 v[4];
#pragma unroll
    for (int q = 0; q < 4; q++) v[q] = ((const float4*)rowp)[tid + q * 256];

    float mx = -3.0e38f;
#pragma unroll
    for (int q = 0; q < 4; q++)
        mx = fmaxf(mx, fmaxf(fmaxf(v[q].x, v[q].y), fmaxf(v[q].z, v[q].w)));
#pragma unroll
    for (int o = 16; o; o >>= 1) mx = fmaxf(mx, __shfl_xor_sync(0xffffffffu, mx, o));
    if ((tid & 31) == 0) sm[tid >> 5] = mx;
    __syncthreads();
    mx = sm[0];
#pragma unroll
    for (int w = 1; w < 8; w++) mx = fmaxf(mx, sm[w]);
    __syncthreads();

    float s = 0.0f;
#pragma unroll
    for (int q = 0; q < 4; q++) {
        v[q].x = expf(v[q].x - mx); v[q].y = expf(v[q].y - mx);
        v[q].z = expf(v[q].z - mx); v[q].w = expf(v[q].w - mx);
        s += (v[q].x + v[q].y) + (v[q].z + v[q].w);
    }
#pragma unroll
    for (int o = 16; o; o >>= 1) s += __shfl_xor_sync(0xffffffffu, s, o);
    if ((tid & 31) == 0) sm[tid >> 5] = s;
    __syncthreads();
    s = sm[0];
#pragma unroll
    for (int w = 1; w < 8; w++) s += sm[w];

    const float inv = 1.0f / s;
    uint32_t* hi_w = (uint32_t*)(g_att_hi + row * HW_);
    uint32_t* lo_w = (uint32_t*)(g_att_lo + row * HW_);
#pragma unroll
    for (int q = 0; q < 4; q++) {
        uint32_t h0, l0, h1, l1;
        split2(v[q].x * inv, v[q].y * inv, h0, l0);
        split2(v[q].z * inv, v[q].w * inv, h1, l1);
        int idx = (tid + q * 256) * 2;
        hi_w[idx] = h0; hi_w[idx + 1] = h1;
        lo_w[idx] = l0; lo_w[idx + 1] = l1;
    }
}

// ===========================================================================
// GEMM2: out[b,n,c] = sum_h att[b,n,h] * feats[b,c,h]   (all bf16 pre-split)
//   CTA tile [c=128 x n=80], K-chunk 64, grid (4, 32) = 128 CTAs (1 wave),
//   512 threads = 16 warps (8 m x 2 n), warp tile m16 x n40.
//   Stage: Fh@0(16384) Fl@16384, Ah@32768(10240) Al@43008. Stage=53248, x2.
// ===========================================================================
__global__ __launch_bounds__(512, 1) void gemm2_mma(float* __restrict__ out) {
    extern __shared__ __align__(1024) char smem[];
    const uint32_t sb = smem_u32(smem);
    const int tid = threadIdx.x, wid = tid >> 5, lane = tid & 31;
    const int g = lane >> 2, t = lane & 3;
    const int mw = wid & 7, nw = wid >> 3;   // m0 = mw*16 (c), n0 = nw*40 (n)
    const int m0 = mw * 16, n0 = nw * 40;
    const int b = blockIdx.y, c0 = blockIdx.x * 128;

    const char* FHb = (const char*)g_f_hi + ((size_t)(b * C_ + c0) * HW_) * 2;
    const char* FLb = (const char*)g_f_lo + ((size_t)(b * C_ + c0) * HW_) * 2;
    const char* AHb = (const char*)g_att_hi + ((size_t)b * N_ * HW_) * 2;
    const char* ALb = (const char*)g_att_lo + ((size_t)b * N_ * HW_) * 2;

    float acc[5][4];
#pragma unroll
    for (int j = 0; j < 5; j++)
#pragma unroll
        for (int k = 0; k < 4; k++) acc[j][k] = 0.0f;

    auto cp_tile = [&](uint32_t buf, int kb) {
        const int hkb = kb * 128;                      // byte offset along h
#pragma unroll
        for (int it = 0; it < 7; it++) {
            int p = tid + it * 512;                    // 3328 chunks of 16B
            if (p < 3328) {
                uint32_t dst; const char* src;
                if (p < 2048) {                        // F: 1024 hi + 1024 lo
                    int sel = p >> 10, q = p & 1023;
                    int c = q >> 3, cb = (q & 7) * 16;
                    src = (sel ? FLb : FHb) + (size_t)c * (HW_ * 2) + hkb + cb;
                    dst = buf + (uint32_t)sel * 16384u + swz((uint32_t)(c * 128 + cb));
                } else {                               // att: 640 hi + 640 lo
                    int q = p - 2048;
                    int sel = q >= 640;
                    int r = sel ? q - 640 : q;
                    int n = r >> 3, cb = (r & 7) * 16;
                    src = (sel ? ALb : AHb) + (size_t)n * (HW_ * 2) + hkb + cb;
                    dst = buf + 32768u + (uint32_t)sel * 10240u +
                          swz((uint32_t)(n * 128 + cb));
                }
                CP_ASYNC16(dst, src);
            }
        }
    };
    auto compute = [&](uint32_t buf) {
        const uint32_t Fh = buf, Fl = buf + 16384u;
        const uint32_t Bh = buf + 32768u, Bl = buf + 43008u;
        const uint32_t arow = (uint32_t)(m0 + (lane & 15)) * 128;
#pragma unroll
        for (int ks = 0; ks < 4; ks++) {
            const uint32_t kc = ks * 32 + (lane >> 4) * 16;
            uint32_t ah[4], al[4];
            uint32_t aoff = swz(arow + kc);
            ldmx4(ah, Fh + aoff);
            ldmx4(al, Fl + aoff);
            uint32_t bh[2][4], bl[2][4], bh2[2], bl2[2];
#pragma unroll
            for (int j = 0; j < 2; j++) {
                uint32_t boff = swz((uint32_t)(n0 + j * 16 + (lane & 15)) * 128 + kc);
                ldmx4(bh[j], Bh + boff);
                ldmx4(bl[j], Bl + boff);
            }
            {
                uint32_t boff = swz((uint32_t)(n0 + 32 + (lane & 7)) * 128 +
                                    ks * 32 + ((lane >> 3) & 1) * 16);
                ldmx2(bh2, Bh + boff);
                ldmx2(bl2, Bl + boff);
            }
            // term-grouped issue: chains per accumulator spaced by 5 indep MMAs
            mma16816(acc[0], ah, bh[0][0], bh[0][2]);      // hi*hi
            mma16816(acc[1], ah, bh[0][1], bh[0][3]);
            mma16816(acc[2], ah, bh[1][0], bh[1][2]);
            mma16816(acc[3], ah, bh[1][1], bh[1][3]);
            mma16816(acc[4], ah, bh2[0],   bh2[1]);
            mma16816(acc[0], ah, bl[0][0], bl[0][2]);      // hi*lo
            mma16816(acc[1], ah, bl[0][1], bl[0][3]);
            mma16816(acc[2], ah, bl[1][0], bl[1][2]);
            mma16816(acc[3], ah, bl[1][1], bl[1][3]);
            mma16816(acc[4], ah, bl2[0],   bl2[1]);
            mma16816(acc[0], al, bh[0][0], bh[0][2]);      // lo*hi
            mma16816(acc[1], al, bh[0][1], bh[0][3]);
            mma16816(acc[2], al, bh[1][0], bh[1][2]);
            mma16816(acc[3], al, bh[1][1], bh[1][3]);
            mma16816(acc[4], al, bh2[0],   bh2[1]);
        }
    };

    cp_tile(sb, 0); CP_COMMIT();
    CP_WAIT0();
    __syncthreads();
#pragma unroll 1
    for (int kb = 0; kb < 64; kb++) {
        const uint32_t cur = sb + (uint32_t)(kb & 1) * G2_STAGE;
        const uint32_t nxt = sb + (uint32_t)((kb + 1) & 1) * G2_STAGE;
        if (kb + 1 < 64) { cp_tile(nxt, kb + 1); CP_COMMIT(); }
        compute(cur);
        if (kb + 1 < 64) {
            CP_WAIT0();
            __syncthreads();
        }
    }

    // epilogue: out[b, n, c]
    {
        int c = c0 + m0 + g;
#pragma unroll
        for (int nf = 0; nf < 5; nf++) {
            int n = n0 + nf * 8 + 2 * t;
            float* p = out + ((size_t)b * N_ + n) * C_ + c;
            p[0]      = acc[nf][0];
            p[C_]     = acc[nf][1];
            p[8]      = acc[nf][2];
            p[C_ + 8] = acc[nf][3];
        }
    }
}

// ---------------------------------------------------------------------------
#define G1_SMEM (2 * 53248)
#define G2_SMEM (2 * 53248)

extern "C" void kernel_launch(void* const* d_in, const int* in_sizes, int n_in,
                              void* d_out, int out_size) {
    const float* feats = (const float*)d_in[0];  // [32, 512, 4096]
    const float* W     = (const float*)d_in[1];  // [80, 512]
    float* out         = (float*)d_out;          // [32, 80, 512]

    cudaFuncSetAttribute(gemm1_mma, cudaFuncAttributeMaxDynamicSharedMemorySize, G1_SMEM);
    cudaFuncSetAttribute(gemm2_mma, cudaFuncAttributeMaxDynamicSharedMemorySize, G2_SMEM);

    split_w<<<80, 256>>>(W);
    gemm1_mma<<<dim3(HW_ / 128, B_), 640, G1_SMEM>>>(feats);
    softmax_split<<<B_ * N_, 256>>>();
    gemm2_mma<<<dim3(4, B_), 512, G2_SMEM>>>(out);
}

// round 8
// speedup vs baseline: 1.0389x; 1.0389x over previous
#include <cuda_runtime.h>
#include <cstdint>

#define B_  32
#define C_  512
#define HW_ 4096
#define N_  80

// Scratch (__device__ globals per allocation rules)
__device__ float g_logits[(size_t)B_ * N_ * HW_];
__device__ float g_att[(size_t)B_ * N_ * HW_];      // softmax output, tf32-rounded f32
__device__ float g_w_r[N_ * C_];                    // W, tf32-rounded f32

// ---------------------------------------------------------------------------
// helpers
// ---------------------------------------------------------------------------
__device__ __forceinline__ uint32_t smem_u32(const void* p) {
    uint32_t a;
    asm("{ .reg .u64 t; cvta.to.shared.u64 t, %1; cvt.u32.u64 %0, t; }" : "=r"(a) : "l"(p));
    return a;
}
#define CP_ASYNC16(dst, src) \
    asm volatile("cp.async.cg.shared.global [%0], [%1], 16;" :: "r"(dst), "l"(src))
#define CP_COMMIT() asm volatile("cp.async.commit_group;" ::: "memory")
#define CP_WAIT1()  asm volatile("cp.async.wait_group 1;" ::: "memory")

__device__ __forceinline__ uint32_t lds_b32(uint32_t addr) {
    uint32_t v;
    asm volatile("ld.shared.b32 %0, [%1];" : "=r"(v) : "r"(addr));
    return v;
}
__device__ __forceinline__ float lds_f32(uint32_t addr) {
    float v;
    asm volatile("ld.shared.f32 %0, [%1];" : "=f"(v) : "r"(addr));
    return v;
}
#define CVT_TF32(u, f) asm("cvt.rna.tf32.f32 %0, %1;" : "=r"(u) : "f"(f))

// D(f32) += A(tf32) * B(tf32), m16n8k8
__device__ __forceinline__ void mma_tf32(float* d, const uint32_t* a,
                                         uint32_t b0, uint32_t b1) {
    asm("mma.sync.aligned.m16n8k8.row.col.f32.tf32.tf32.f32 "
        "{%0,%1,%2,%3}, {%4,%5,%6,%7}, {%8,%9}, {%0,%1,%2,%3};"
        : "+f"(d[0]), "+f"(d[1]), "+f"(d[2]), "+f"(d[3])
        : "r"(a[0]), "r"(a[1]), "r"(a[2]), "r"(a[3]), "r"(b0), "r"(b1));
}

// ===========================================================================
// w_round: W f32 -> tf32-rounded f32. grid 160, block 256.
// ===========================================================================
__global__ void w_round(const float* __restrict__ W) {
    int i = blockIdx.x * 256 + threadIdx.x;     // 40960 elems
    uint32_t r; CVT_TF32(r, W[i]);
    g_w_r[i] = __uint_as_float(r);
}

// ===========================================================================
// GEMM1: logits[b,n,h] = sum_c W[n,c] * feats[b,c,h]    (tf32 single-pass)
//   CTA tile [n=80 x h=128]. 640 threads = 20 warps (5 m x 4 hq),
//   warp tile m16(n) x n32(h). W [80 x 512] preloaded to smem (stride 2064B),
//   feats chunks k=32 [32 x 128] f32 (stride 544B), 3-stage cp.async.
// ===========================================================================
#define W_STRIDE  2064u
#define W_BYTES   (80u * W_STRIDE)              // 165120
#define B1_STRIDE 544u
#define B1_CHUNK  (32u * B1_STRIDE)             // 17408
#define G1_SMEM   (W_BYTES + 3u * B1_CHUNK)     // 217344

__global__ __launch_bounds__(640, 1) void gemm1_mma(const float* __restrict__ feats) {
    extern __shared__ __align__(1024) char smem[];
    const uint32_t sb = smem_u32(smem);
    const int tid = threadIdx.x, wid = tid >> 5, lane = tid & 31;
    const int g = lane >> 2, t = lane & 3;
    const int mw = wid % 5, hq = wid / 5;
    const int m0 = mw * 16, h0w = hq * 32;
    const int b = blockIdx.y, hC = blockIdx.x * 128;

    const char* FbB = (const char*)(feats + (size_t)b * C_ * HW_);
    const uint32_t wbase = sb;
    const uint32_t bbase = sb + W_BYTES;

    float acc[4][4];
#pragma unroll
    for (int i = 0; i < 4; i++)
#pragma unroll
        for (int j = 0; j < 4; j++) acc[i][j] = 0.0f;

    // W preload (goes into commit group 0 along with chunk 0)
    {
        const char* wsrc = (const char*)g_w_r;
#pragma unroll
        for (int it = 0; it < 16; it++) {
            int p = tid + it * 640;              // 10240 16B chunks
            int n = p >> 7, cb = (p & 127) * 16;
            CP_ASYNC16(wbase + (uint32_t)(n * W_STRIDE) + cb, wsrc + n * 2048 + cb);
        }
    }
    auto cp_b = [&](int kb) {
        const uint32_t dst0 = bbase + (uint32_t)(kb % 3) * B1_CHUNK;
#pragma unroll
        for (int it = 0; it < 2; it++) {
            int p = tid + it * 640;              // 1024 16B chunks
            if (p < 1024) {
                int r = p >> 5, cb = (p & 31) * 16;
                CP_ASYNC16(dst0 + (uint32_t)(r * B1_STRIDE) + cb,
                           FbB + ((size_t)(kb * 32 + r) * HW_ + hC) * 4 + cb);
            }
        }
    };
    auto compute = [&](int kb) {
        const uint32_t bb = bbase + (uint32_t)(kb % 3) * B1_CHUNK;
#pragma unroll
        for (int ks = 0; ks < 4; ks++) {
            const int kkg = kb * 32 + ks * 8;
            uint32_t a[4];
            const uint32_t ar0 = wbase + (uint32_t)(m0 + g) * W_STRIDE + (kkg + t) * 4;
            const uint32_t ar1 = ar0 + 8 * W_STRIDE;
            a[0] = lds_b32(ar0);       a[1] = lds_b32(ar1);
            a[2] = lds_b32(ar0 + 16);  a[3] = lds_b32(ar1 + 16);
#pragma unroll
            for (int np = 0; np < 4; np++) {
                const uint32_t col4 = (uint32_t)(h0w + np * 8 + g) * 4;
                float f0 = lds_f32(bb + (uint32_t)((ks * 8 + t) * B1_STRIDE) + col4);
                float f1 = lds_f32(bb + (uint32_t)((ks * 8 + t + 4) * B1_STRIDE) + col4);
                uint32_t b0, b1; CVT_TF32(b0, f0); CVT_TF32(b1, f1);
                mma_tf32(acc[np], a, b0, b1);
            }
        }
    };

    cp_b(0); CP_COMMIT();
    cp_b(1); CP_COMMIT();
#pragma unroll 1
    for (int kb = 0; kb < 16; kb++) {
        CP_WAIT1();
        __syncthreads();
        compute(kb);
        if (kb + 2 < 16) cp_b(kb + 2);
        CP_COMMIT();                             // always commit (possibly empty group)
    }

    // epilogue: logits fp32
#pragma unroll
    for (int np = 0; np < 4; np++) {
        int h = hC + h0w + np * 8 + 2 * t;
        int n = m0 + g;
        *(float2*)(g_logits + (size_t)(b * N_ + n) * HW_ + h) =
            make_float2(acc[np][0], acc[np][1]);
        *(float2*)(g_logits + (size_t)(b * N_ + n + 8) * HW_ + h) =
            make_float2(acc[np][2], acc[np][3]);
    }
}

// ===========================================================================
// Softmax over HW -> g_att (tf32-rounded f32). grid B*N, block 256.
// ===========================================================================
__global__ __launch_bounds__(256) void softmax_rnd() {
    const size_t row = blockIdx.x;
    const float* rowp = g_logits + row * HW_;
    const int tid = threadIdx.x;
    __shared__ float sm[8];

    float4 v[4];
#pragma unroll
    for (int q = 0; q < 4; q++) v[q] = ((const float4*)rowp)[tid + q * 256];

    float mx = -3.0e38f;
#pragma unroll
    for (int q = 0; q < 4; q++)
        mx = fmaxf(mx, fmaxf(fmaxf(v[q].x, v[q].y), fmaxf(v[q].z, v[q].w)));
#pragma unroll
    for (int o = 16; o; o >>= 1) mx = fmaxf(mx, __shfl_xor_sync(0xffffffffu, mx, o));
    if ((tid & 31) == 0) sm[tid >> 5] = mx;
    __syncthreads();
    mx = sm[0];
#pragma unroll
    for (int w = 1; w < 8; w++) mx = fmaxf(mx, sm[w]);
    __syncthreads();

    float s = 0.0f;
#pragma unroll
    for (int q = 0; q < 4; q++) {
        v[q].x = expf(v[q].x - mx); v[q].y = expf(v[q].y - mx);
        v[q].z = expf(v[q].z - mx); v[q].w = expf(v[q].w - mx);
        s += (v[q].x + v[q].y) + (v[q].z + v[q].w);
    }
#pragma unroll
    for (int o = 16; o; o >>= 1) s += __shfl_xor_sync(0xffffffffu, s, o);
    if ((tid & 31) == 0) sm[tid >> 5] = s;
    __syncthreads();
    s = sm[0];
#pragma unroll
    for (int w = 1; w < 8; w++) s += sm[w];

    const float inv = 1.0f / s;
    float* ow = g_att + row * HW_;
#pragma unroll
    for (int q = 0; q < 4; q++) {
        uint32_t r0, r1, r2, r3;
        CVT_TF32(r0, v[q].x * inv); CVT_TF32(r1, v[q].y * inv);
        CVT_TF32(r2, v[q].z * inv); CVT_TF32(r3, v[q].w * inv);
        float4 o;
        o.x = __uint_as_float(r0); o.y = __uint_as_float(r1);
        o.z = __uint_as_float(r2); o.w = __uint_as_float(r3);
        ((float4*)ow)[tid + q * 256] = o;
    }
}

// ===========================================================================
// GEMM2: out[b,n,c] = sum_h att[b,n,h] * feats[b,c,h]    (tf32 single-pass)
//   CTA tile [c=128 x n=80], grid (4, 32) = 128 CTAs, 512 threads = 16 warps
//   (8 m x 2 n), warp tile m16(c) x n40. Chunks k=64:
//   A = feats [128 x 64] f32 (stride 272B), B = att [80 x 64] f32 (stride 272B),
//   3-stage cp.async.
// ===========================================================================
#define A2_STRIDE 272u
#define A2_BYTES  (128u * A2_STRIDE)            // 34816
#define B2_BYTES  (80u * A2_STRIDE)             // 21760
#define G2_STAGE  (A2_BYTES + B2_BYTES)         // 56576
#define G2_SMEM   (3u * G2_STAGE)               // 169728

__global__ __launch_bounds__(512, 1) void gemm2_mma(const float* __restrict__ feats,
                                                    float* __restrict__ out) {
    extern __shared__ __align__(1024) char smem[];
    const uint32_t sb = smem_u32(smem);
    const int tid = threadIdx.x, wid = tid >> 5, lane = tid & 31;
    const int g = lane >> 2, t = lane & 3;
    const int mw = wid & 7, nw = wid >> 3;
    const int m0 = mw * 16, n0 = nw * 40;
    const int b = blockIdx.y, c0 = blockIdx.x * 128;

    const char* FbB = (const char*)(feats + (size_t)(b * C_ + c0) * HW_);
    const char* AbB = (const char*)(g_att + (size_t)b * N_ * HW_);

    float acc[5][4];
#pragma unroll
    for (int j = 0; j < 5; j++)
#pragma unroll
        for (int k = 0; k < 4; k++) acc[j][k] = 0.0f;

    auto cp_tile = [&](int kb) {
        const uint32_t buf = sb + (uint32_t)(kb % 3) * G2_STAGE;
        const int hkb = kb * 256;                // byte offset along h
#pragma unroll
        for (int it = 0; it < 7; it++) {
            int p = tid + it * 512;              // 3328 16B chunks
            if (p < 3328) {
                if (p < 2048) {                  // feats: 128 rows x 16 chunks
                    int c = p >> 4, cb = (p & 15) * 16;
                    CP_ASYNC16(buf + (uint32_t)(c * A2_STRIDE) + cb,
                               FbB + (size_t)c * (HW_ * 4) + hkb + cb);
                } else {                         // att: 80 rows x 16 chunks
                    int q = p - 2048;
                    int n = q >> 4, cb = (q & 15) * 16;
                    CP_ASYNC16(buf + A2_BYTES + (uint32_t)(n * A2_STRIDE) + cb,
                               AbB + (size_t)n * (HW_ * 4) + hkb + cb);
                }
            }
        }
    };
    auto compute = [&](int kb) {
        const uint32_t Fs = sb + (uint32_t)(kb % 3) * G2_STAGE;
        const uint32_t Bs = Fs + A2_BYTES;
#pragma unroll
        for (int ks = 0; ks < 8; ks++) {
            const uint32_t kk4 = (uint32_t)(ks * 8 + t) * 4;
            // A = feats rows m0+g, m0+g+8 (cvt to tf32 in-register)
            const uint32_t ar0 = Fs + (uint32_t)(m0 + g) * A2_STRIDE + kk4;
            const uint32_t ar1 = ar0 + 8 * A2_STRIDE;
            float af0 = lds_f32(ar0),      af1 = lds_f32(ar1);
            float af2 = lds_f32(ar0 + 16), af3 = lds_f32(ar1 + 16);
            uint32_t a[4];
            CVT_TF32(a[0], af0); CVT_TF32(a[1], af1);
            CVT_TF32(a[2], af2); CVT_TF32(a[3], af3);
#pragma unroll
            for (int nf = 0; nf < 5; nf++) {
                const uint32_t br = Bs + (uint32_t)(n0 + nf * 8 + g) * A2_STRIDE + kk4;
                uint32_t b0 = lds_b32(br);        // att pre-rounded
                uint32_t b1 = lds_b32(br + 16);
                mma_tf32(acc[nf], a, b0, b1);
            }
        }
    };

    cp_tile(0); CP_COMMIT();
    cp_tile(1); CP_COMMIT();
#pragma unroll 1
    for (int kb = 0; kb < 64; kb++) {
        CP_WAIT1();
        __syncthreads();
        compute(kb);
        if (kb + 2 < 64) cp_tile(kb + 2);
        CP_COMMIT();                             // always commit (possibly empty group)
    }

    // epilogue: out[b, n, c]
    {
        int c = c0 + m0 + g;
#pragma unroll
        for (int nf = 0; nf < 5; nf++) {
            int n = n0 + nf * 8 + 2 * t;
            float* p = out + ((size_t)b * N_ + n) * C_ + c;
            p[0]      = acc[nf][0];
            p[C_]     = acc[nf][1];
            p[8]      = acc[nf][2];
            p[C_ + 8] = acc[nf][3];
        }
    }
}

// ---------------------------------------------------------------------------
extern "C" void kernel_launch(void* const* d_in, const int* in_sizes, int n_in,
                              void* d_out, int out_size) {
    const float* feats = (const float*)d_in[0];  // [32, 512, 4096]
    const float* W     = (const float*)d_in[1];  // [80, 512]
    float* out         = (float*)d_out;          // [32, 80, 512]

    cudaFuncSetAttribute(gemm1_mma, cudaFuncAttributeMaxDynamicSharedMemorySize, G1_SMEM);
    cudaFuncSetAttribute(gemm2_mma, cudaFuncAttributeMaxDynamicSharedMemorySize, G2_SMEM);

    w_round<<<160, 256>>>(W);
    gemm1_mma<<<dim3(HW_ / 128, B_), 640, G1_SMEM>>>(feats);
    softmax_rnd<<<B_ * N_, 256>>>();
    gemm2_mma<<<dim3(4, B_), 512, G2_SMEM>>>(feats, out);
}